// round 8
// baseline (speedup 1.0000x reference)
#include <cuda_runtime.h>
#include <cstdint>
#include <cstddef>

#define BB 2
#define NN 512
#define KK 128
#define EE 768
#define NEDGE 1536

// output layout: edge_feature [B,N,N,K] | merge [B,N,E] | delta_pos [B,N,N,3]
#define OFF_EF    ((size_t)0)
#define OFF_MERGE ((size_t)BB*NN*NN*KK)                 // 67108864
#define OFF_DP    (OFF_MERGE + (size_t)BB*NN*EE)        // 67895296

__device__ __align__(16) float g_t2[BB][KK];   // 2 * t_enc(time_pos[b])
__device__ __align__(16) float g_t02[KK];      // 2 * t_enc(0)
__device__ __align__(16) float g_sum[BB*NN*KK];
__device__ int g_mask_is_byte;
__device__ int g_flag = 0;                     // tenc-done flag (self-resetting)
__device__ int g_done = 0;                     // edge-blocks-finished counter

__device__ __forceinline__ int maskv(const void* p, int idx, int isb) {
    return isb ? (int)((const unsigned char*)p)[idx] : ((const int*)p)[idx];
}

// ---------------------------------------------------------------------------
// Fused kernel: block 0 = timestep-encoder MLP (+ sets g_flag);
// blocks 1..BB*NN = edge rows (spin on g_flag only at phase-2 entry).
// ---------------------------------------------------------------------------
__global__ void __launch_bounds__(128) fused_kernel(
    const float* __restrict__ pos,
    const int*   __restrict__ nte,
    const void*  __restrict__ pad_m,
    const void*  __restrict__ aa_m,
    const void*  __restrict__ pos_m,
    const int*   __restrict__ time_pos,
    const float* __restrict__ means,
    const float* __restrict__ stds,
    const float* __restrict__ mul_w,
    const float* __restrict__ bias_w,
    const float* __restrict__ w1, const float* __restrict__ b1,
    const float* __restrict__ w2, const float* __restrict__ b2,
    float* __restrict__ out)
{
    const int tid  = threadIdx.x;
    const int lane = tid & 31;
    const int warp = tid >> 5;

    __shared__ float4 pk[NN];            // (x, padf, mdf, -)   8KB
    __shared__ float  ppos[NN * 3];      //                     6KB
    __shared__ float2 tbl[NEDGE];        // (mul, bias)        12KB
    __shared__ float4 partial[4][32];    //                     2KB

    // ======================= block 0: timestep encoder ======================
    if (blockIdx.x == 0) {
        // overlay MLP scratch on pk (block 0 never runs edge phase)
        float* es  = (float*)pk;           // es[3][KK]
        float* hsv = es + 3 * KK;          // hsv[3][KK]

        float tv0 = (float)time_pos[0];
        float tv1 = (float)time_pos[1];
        int h = (tid < 64) ? tid : tid - 64;
        float fr = __expf(-9.210340371976184f * (float)h * (1.0f / 64.0f));
        if (tid < 64) {
            es[0 * KK + tid] = cosf(tv0 * fr);
            es[1 * KK + tid] = cosf(tv1 * fr);
            es[2 * KK + tid] = 1.0f;                 // cos(0)
        } else {
            es[0 * KK + tid] = sinf(tv0 * fr);
            es[1 * KK + tid] = sinf(tv1 * fr);
            es[2 * KK + tid] = 0.0f;                 // sin(0)
        }
        __syncthreads();

        // layer 1: shared weight load, 3 cases per load
        {
            float a0 = 0.f, a1 = 0.f, a2 = 0.f;
            #pragma unroll 16
            for (int k = 0; k < KK; k++) {
                float w = w1[k * KK + tid];
                a0 = fmaf(es[0 * KK + k], w, a0);
                a1 = fmaf(es[1 * KK + k], w, a1);
                a2 = fmaf(es[2 * KK + k], w, a2);
            }
            float bb = b1[tid];
            float x0 = a0 + bb, x1 = a1 + bb, x2 = a2 + bb;
            hsv[0 * KK + tid] = x0 / (1.0f + __expf(-x0));
            hsv[1 * KK + tid] = x1 / (1.0f + __expf(-x1));
            hsv[2 * KK + tid] = x2 / (1.0f + __expf(-x2));
        }
        __syncthreads();

        // layer 2
        {
            float a0 = 0.f, a1 = 0.f, a2 = 0.f;
            #pragma unroll 16
            for (int k = 0; k < KK; k++) {
                float w = w2[k * KK + tid];
                a0 = fmaf(hsv[0 * KK + k], w, a0);
                a1 = fmaf(hsv[1 * KK + k], w, a1);
                a2 = fmaf(hsv[2 * KK + k], w, a2);
            }
            float bb = b2[tid];
            g_t2[0][tid] = (a0 + bb) * 2.0f;
            g_t2[1][tid] = (a1 + bb) * 2.0f;
            g_t02[tid]   = (a2 + bb) * 2.0f;
        }

        // mask-format detection for proj kernel
        {
            unsigned int wv = ((const unsigned int*)pad_m)[tid];
            int any = __syncthreads_or(wv > 1u);
            if (tid == 0) g_mask_is_byte = any ? 1 : 0;
        }

        __threadfence();                 // release g_t2/g_t02
        __syncthreads();
        if (tid == 0) atomicExch(&g_flag, 1);
        return;
    }

    // =========================== edge blocks ================================
    const int idx = blockIdx.x - 1;
    const int b = idx >> 9;
    const int i = idx & 511;

    // local mask-format detection (cannot wait for block 0 before phase 1)
    unsigned int wv = ((const unsigned int*)pad_m)[tid];
    const int isb = __syncthreads_or(wv > 1u) ? 1 : 0;

    // vectorized prologue
    {
        const float4* p4 = (const float4*)(pos + b * NN * 3);   // 384 float4
        float4* s4 = (float4*)ppos;
        for (int t = tid; t < 384; t += 128) s4[t] = p4[t];

        const float4* m4 = (const float4*)mul_w;                // 384 float4
        const float4* b4 = (const float4*)bias_w;
        for (int t = tid; t < 384; t += 128) {
            float4 m = m4[t], bq = b4[t];
            tbl[t * 4 + 0] = make_float2(m.x, bq.x);
            tbl[t * 4 + 1] = make_float2(m.y, bq.y);
            tbl[t * 4 + 2] = make_float2(m.z, bq.z);
            tbl[t * 4 + 3] = make_float2(m.w, bq.w);
        }
    }
    __syncthreads();

    const float pix = ppos[i * 3 + 0], piy = ppos[i * 3 + 1], piz = ppos[i * 3 + 2];
    const int aa_i = maskv(aa_m,  b * NN + i, isb);
    const int mp_i = maskv(pos_m, b * NN + i, isb);

    float* dpo = out + OFF_DP + ((size_t)(b * NN + i)) * (size_t)NN * 3;
    const int4* nrow4 = (const int4*)(nte + ((size_t)(b * NN + i)) * (size_t)NN * 2);

    // ---- Phase 1: per-j scalars (2 j's per iter via int4 edge loads) -------
    #pragma unroll
    for (int jt2 = tid; jt2 < NN / 2; jt2 += 128) {
        int4 e4 = nrow4[jt2];
        #pragma unroll
        for (int h = 0; h < 2; h++) {
            int jt = jt2 * 2 + h;
            float dx = ppos[jt * 3 + 0] - pix;
            float dy = ppos[jt * 3 + 1] - piy;
            float dz = ppos[jt * 3 + 2] - piz;
            float dist = sqrtf(dx * dx + dy * dy + dz * dz);
            float rinv = __fdividef(1.0f, dist + 1e-5f);
            dpo[jt * 3 + 0] = dx * rinv;
            dpo[jt * 3 + 1] = dy * rinv;
            dpo[jt * 3 + 2] = dz * rinv;

            int exi = h ? e4.z : e4.x;
            int eyi = h ? e4.w : e4.y;
            int aa_j = maskv(aa_m, b * NN + jt, isb);
            float2 t0 = tbl[aa_i ? 0 : exi];
            float2 t1 = tbl[aa_j ? 0 : eyi];
            float mul = t0.x + t1.x;
            float bia = t0.y + t1.y;

            int padj = maskv(pad_m, b * NN + jt, isb);
            int md   = mp_i | maskv(pos_m, b * NN + jt, isb);
            pk[jt] = make_float4(fmaf(mul, dist, bia),
                                 padj ? 0.0f : 1.0f,
                                 md   ? 1.0f : 0.0f, 0.0f);
        }
    }
    __syncthreads();

    // ---- wait for timestep encoder (block 0) -------------------------------
    if (tid == 0) {
        while (*(volatile int*)&g_flag == 0) __nanosleep(64);
    }
    __syncthreads();

    // ---- per-thread k-quad parameters (t vectors via L2 to skip stale L1) --
    const int k0 = lane * 4;
    float4 mn = *(const float4*)(means + k0);
    float4 sd = *(const float4*)(stds + k0);
    float is_x = 1.0f / (fabsf(sd.x) + 0.01f);
    float is_y = 1.0f / (fabsf(sd.y) + 0.01f);
    float is_z = 1.0f / (fabsf(sd.z) + 0.01f);
    float is_w = 1.0f / (fabsf(sd.w) + 0.01f);
    const float inv_a = 0.39894290f;           // 1/sqrt(2*3.14159)
    float cf_x = is_x * inv_a, cf_y = is_y * inv_a, cf_z = is_z * inv_a, cf_w = is_w * inv_a;
    float mi_x = mn.x * is_x, mi_y = mn.y * is_y, mi_z = mn.z * is_z, mi_w = mn.w * is_w;

    float4 t2v  = __ldcg((const float4*)(&g_t2[b][k0]));
    float4 t02v = __ldcg((const float4*)(&g_t02[k0]));
    float dt_x = t2v.x - t02v.x, dt_y = t2v.y - t02v.y;
    float dt_z = t2v.z - t02v.z, dt_w = t2v.w - t02v.w;

    float* efb = out + OFF_EF + ((size_t)(b * NN + i)) * (size_t)(NN * KK);
    float4 acc = make_float4(0.f, 0.f, 0.f, 0.f);
    const float4 zero4 = make_float4(0.f, 0.f, 0.f, 0.f);

    // ---- Phase 2: warp owns j%4, lane owns k-quad. Branch is warp-uniform. --
    #pragma unroll 8
    for (int jb = 0; jb < NN / 4; jb++) {
        int j = jb * 4 + warp;
        float4 p = pk[j];
        float4* dst = (float4*)(efb + (size_t)j * KK + k0);

        if (p.y == 0.0f) {
            __stcs(dst, zero4);               // padded j: whole K row zero
        } else {
            float x = p.x, mdf = p.z;

            float zx = fmaf(x, is_x, -mi_x);
            float zy = fmaf(x, is_y, -mi_y);
            float zz = fmaf(x, is_z, -mi_z);
            float zw = fmaf(x, is_w, -mi_w);
            float gx = __expf(zx * zx * -0.5f);
            float gy = __expf(zy * zy * -0.5f);
            float gz = __expf(zz * zz * -0.5f);
            float gw = __expf(zw * zw * -0.5f);

            float4 r;
            r.x = fmaf(gx, cf_x, fmaf(mdf, dt_x, t02v.x));
            r.y = fmaf(gy, cf_y, fmaf(mdf, dt_y, t02v.y));
            r.z = fmaf(gz, cf_z, fmaf(mdf, dt_z, t02v.z));
            r.w = fmaf(gw, cf_w, fmaf(mdf, dt_w, t02v.w));

            acc.x += r.x; acc.y += r.y; acc.z += r.z; acc.w += r.w;
            __stcs(dst, r);
        }
    }

    // ---- row-sum reduction across the 4 warps ------------------------------
    partial[warp][lane] = acc;
    __syncthreads();
    if (warp == 0) {
        float4 a0 = partial[0][lane], a1 = partial[1][lane];
        float4 a2 = partial[2][lane], a3 = partial[3][lane];
        float4 s = make_float4(a0.x + a1.x + a2.x + a3.x,
                               a0.y + a1.y + a2.y + a3.y,
                               a0.z + a1.z + a2.z + a3.z,
                               a0.w + a1.w + a2.w + a3.w);
        *(float4*)(&g_sum[((size_t)(b * NN + i)) * KK + k0]) = s;
    }

    // ---- self-reset of flag/done for the next graph replay -----------------
    if (tid == 0) {
        int old = atomicAdd(&g_done, 1);
        if (old == BB * NN - 1) {            // last edge block out
            g_done = 0;
            __threadfence();
            *(volatile int*)&g_flag = 0;
        }
    }
}

// ---------------------------------------------------------------------------
// Kernel 3: merge = sum_edge_features @ proj_w + proj_b (zero padded rows).
// Latency-optimized: tile 8 rows x 256 cols, grid (128,3) = 384 blocks.
// Thread owns e-quad x 2 rows: per k = 1 independent LDG.128 + broadcast
// LDS.64 + 8 FMA; unroll 8 keeps 8 wide loads in flight.
// ---------------------------------------------------------------------------
__global__ void __launch_bounds__(256) proj_kernel(
    const float* __restrict__ pw, const float* __restrict__ pb,
    const void* __restrict__ pad_m, float* __restrict__ out)
{
    __shared__ __align__(16) float s_t[KK * 8];    // [k][row], 4KB
    const int bx  = blockIdx.x;                    // row tile (8 rows)
    const int tid = threadIdx.x;
    const int eq  = tid & 63;                      // e-quad within 256-col tile
    const int rg  = tid >> 6;                      // row-group 0..3 (2 rows each)
    const int e0  = blockIdx.y * 256 + eq * 4;

    // load 8 rows of g_sum, transposed to [k][row]
    for (int idx = tid; idx < 8 * KK; idx += 256) {
        int row = idx >> 7;          // 0..7
        int k   = idx & 127;
        s_t[k * 8 + row] = g_sum[(size_t)bx * 8 * KK + idx];
    }
    __syncthreads();

    float4 acc0 = make_float4(0.f, 0.f, 0.f, 0.f);
    float4 acc1 = make_float4(0.f, 0.f, 0.f, 0.f);

    #pragma unroll 8
    for (int k = 0; k < KK; k++) {
        float4 w = *(const float4*)(pw + (size_t)k * EE + e0);
        float2 sv = *(const float2*)(s_t + k * 8 + rg * 2);
        acc0.x = fmaf(sv.x, w.x, acc0.x);
        acc0.y = fmaf(sv.x, w.y, acc0.y);
        acc0.z = fmaf(sv.x, w.z, acc0.z);
        acc0.w = fmaf(sv.x, w.w, acc0.w);
        acc1.x = fmaf(sv.y, w.x, acc1.x);
        acc1.y = fmaf(sv.y, w.y, acc1.y);
        acc1.z = fmaf(sv.y, w.z, acc1.z);
        acc1.w = fmaf(sv.y, w.w, acc1.w);
    }

    float4 bias = *(const float4*)(pb + e0);
    int isb = g_mask_is_byte;

    {
        int row = bx * 8 + rg * 2;
        int pm = maskv(pad_m, row, isb);
        float4 r = pm ? make_float4(0.f, 0.f, 0.f, 0.f)
                      : make_float4(acc0.x + bias.x, acc0.y + bias.y,
                                    acc0.z + bias.z, acc0.w + bias.w);
        *(float4*)(out + OFF_MERGE + (size_t)row * EE + e0) = r;
    }
    {
        int row = bx * 8 + rg * 2 + 1;
        int pm = maskv(pad_m, row, isb);
        float4 r = pm ? make_float4(0.f, 0.f, 0.f, 0.f)
                      : make_float4(acc1.x + bias.x, acc1.y + bias.y,
                                    acc1.z + bias.z, acc1.w + bias.w);
        *(float4*)(out + OFF_MERGE + (size_t)row * EE + e0) = r;
    }
}

// ---------------------------------------------------------------------------
extern "C" void kernel_launch(void* const* d_in, const int* in_sizes, int n_in,
                              void* d_out, int out_size)
{
    const float* pos    = (const float*)d_in[0];
    const int*   nte    = (const int*)  d_in[1];
    const void*  pad_m  = d_in[2];
    const void*  aa_m   = d_in[3];
    const void*  pos_m  = d_in[4];
    const int*   time_p = (const int*)  d_in[5];
    const float* means  = (const float*)d_in[6];
    const float* stds   = (const float*)d_in[7];
    const float* mul_w  = (const float*)d_in[8];
    const float* bias_w = (const float*)d_in[9];
    const float* proj_w = (const float*)d_in[10];
    const float* proj_b = (const float*)d_in[11];
    const float* t_w1   = (const float*)d_in[12];
    const float* t_b1   = (const float*)d_in[13];
    const float* t_w2   = (const float*)d_in[14];
    const float* t_b2   = (const float*)d_in[15];
    float* out = (float*)d_out;

    fused_kernel<<<BB * NN + 1, 128>>>(pos, nte, pad_m, aa_m, pos_m, time_p,
                                       means, stds, mul_w, bias_w,
                                       t_w1, t_b1, t_w2, t_b2, out);
    proj_kernel<<<dim3((BB * NN) / 8, EE / 256), 256>>>(proj_w, proj_b, pad_m, out);
}

// round 10
// speedup vs baseline: 1.1657x; 1.1657x over previous
#include <cuda_runtime.h>
#include <cstdint>
#include <cstddef>

#define BB 2
#define NN 512
#define KK 128
#define EE 768
#define NEDGE 1536

// output layout: edge_feature [B,N,N,K] | merge [B,N,E] | delta_pos [B,N,N,3]
#define OFF_EF    ((size_t)0)
#define OFF_MERGE ((size_t)BB*NN*NN*KK)                 // 67108864
#define OFF_DP    (OFF_MERGE + (size_t)BB*NN*EE)        // 67895296

__device__ __align__(16) float g_t2[BB][KK];   // 2 * t_enc(time_pos[b])
__device__ __align__(16) float g_t02[KK];      // 2 * t_enc(0)
__device__ __align__(16) float g_sum[BB*NN*KK];
__device__ int g_mask_is_byte;
__device__ int g_flag = 0;                     // tenc-done flag (self-resetting)
__device__ int g_done = 0;                     // edge-blocks-finished counter

__device__ __forceinline__ int maskv(const void* p, int idx, int isb) {
    return isb ? (int)((const unsigned char*)p)[idx] : ((const int*)p)[idx];
}

// ---------------------------------------------------------------------------
// Fused kernel: block 0 = timestep-encoder MLP (+ sets g_flag);
// blocks 1..BB*NN = edge rows (spin on g_flag only at phase-2 entry).
// ---------------------------------------------------------------------------
__global__ void __launch_bounds__(128) fused_kernel(
    const float* __restrict__ pos,
    const int*   __restrict__ nte,
    const void*  __restrict__ pad_m,
    const void*  __restrict__ aa_m,
    const void*  __restrict__ pos_m,
    const int*   __restrict__ time_pos,
    const float* __restrict__ means,
    const float* __restrict__ stds,
    const float* __restrict__ mul_w,
    const float* __restrict__ bias_w,
    const float* __restrict__ w1, const float* __restrict__ b1,
    const float* __restrict__ w2, const float* __restrict__ b2,
    float* __restrict__ out)
{
    const int tid  = threadIdx.x;
    const int lane = tid & 31;
    const int warp = tid >> 5;

    __shared__ float4 pk[NN];            // (x, padf, mdf, -)   8KB
    __shared__ float  ppos[NN * 3];      //                     6KB
    __shared__ float2 tbl[NEDGE];        // (mul, bias)        12KB
    __shared__ float4 partial[4][32];    //                     2KB

    // ======================= block 0: timestep encoder ======================
    if (blockIdx.x == 0) {
        // overlay MLP scratch on pk (block 0 never runs edge phase)
        float* es  = (float*)pk;           // es[3][KK]
        float* hsv = es + 3 * KK;          // hsv[3][KK]

        float tv0 = (float)time_pos[0];
        float tv1 = (float)time_pos[1];
        int h = (tid < 64) ? tid : tid - 64;
        float fr = __expf(-9.210340371976184f * (float)h * (1.0f / 64.0f));
        if (tid < 64) {
            es[0 * KK + tid] = cosf(tv0 * fr);
            es[1 * KK + tid] = cosf(tv1 * fr);
            es[2 * KK + tid] = 1.0f;                 // cos(0)
        } else {
            es[0 * KK + tid] = sinf(tv0 * fr);
            es[1 * KK + tid] = sinf(tv1 * fr);
            es[2 * KK + tid] = 0.0f;                 // sin(0)
        }
        __syncthreads();

        // layer 1: shared weight load, 3 cases per load
        {
            float a0 = 0.f, a1 = 0.f, a2 = 0.f;
            #pragma unroll 16
            for (int k = 0; k < KK; k++) {
                float w = w1[k * KK + tid];
                a0 = fmaf(es[0 * KK + k], w, a0);
                a1 = fmaf(es[1 * KK + k], w, a1);
                a2 = fmaf(es[2 * KK + k], w, a2);
            }
            float bb = b1[tid];
            float x0 = a0 + bb, x1 = a1 + bb, x2 = a2 + bb;
            hsv[0 * KK + tid] = x0 / (1.0f + __expf(-x0));
            hsv[1 * KK + tid] = x1 / (1.0f + __expf(-x1));
            hsv[2 * KK + tid] = x2 / (1.0f + __expf(-x2));
        }
        __syncthreads();

        // layer 2
        {
            float a0 = 0.f, a1 = 0.f, a2 = 0.f;
            #pragma unroll 16
            for (int k = 0; k < KK; k++) {
                float w = w2[k * KK + tid];
                a0 = fmaf(hsv[0 * KK + k], w, a0);
                a1 = fmaf(hsv[1 * KK + k], w, a1);
                a2 = fmaf(hsv[2 * KK + k], w, a2);
            }
            float bb = b2[tid];
            g_t2[0][tid] = (a0 + bb) * 2.0f;
            g_t2[1][tid] = (a1 + bb) * 2.0f;
            g_t02[tid]   = (a2 + bb) * 2.0f;
        }

        // mask-format detection for proj kernel
        {
            unsigned int wv = ((const unsigned int*)pad_m)[tid];
            int any = __syncthreads_or(wv > 1u);
            if (tid == 0) g_mask_is_byte = any ? 1 : 0;
        }

        __threadfence();                 // release g_t2/g_t02
        __syncthreads();
        if (tid == 0) atomicExch(&g_flag, 1);
        return;
    }

    // =========================== edge blocks ================================
    const int idx = blockIdx.x - 1;
    const int b = idx >> 9;
    const int i = idx & 511;

    // local mask-format detection (cannot wait for block 0 before phase 1)
    unsigned int wv = ((const unsigned int*)pad_m)[tid];
    const int isb = __syncthreads_or(wv > 1u) ? 1 : 0;

    // vectorized prologue
    {
        const float4* p4 = (const float4*)(pos + b * NN * 3);   // 384 float4
        float4* s4 = (float4*)ppos;
        for (int t = tid; t < 384; t += 128) s4[t] = p4[t];

        const float4* m4 = (const float4*)mul_w;                // 384 float4
        const float4* b4 = (const float4*)bias_w;
        for (int t = tid; t < 384; t += 128) {
            float4 m = m4[t], bq = b4[t];
            tbl[t * 4 + 0] = make_float2(m.x, bq.x);
            tbl[t * 4 + 1] = make_float2(m.y, bq.y);
            tbl[t * 4 + 2] = make_float2(m.z, bq.z);
            tbl[t * 4 + 3] = make_float2(m.w, bq.w);
        }
    }
    __syncthreads();

    const float pix = ppos[i * 3 + 0], piy = ppos[i * 3 + 1], piz = ppos[i * 3 + 2];
    const int aa_i = maskv(aa_m,  b * NN + i, isb);
    const int mp_i = maskv(pos_m, b * NN + i, isb);

    float* dpo = out + OFF_DP + ((size_t)(b * NN + i)) * (size_t)NN * 3;
    const int4* nrow4 = (const int4*)(nte + ((size_t)(b * NN + i)) * (size_t)NN * 2);

    // ---- Phase 1: per-j scalars (2 j's per iter via int4 edge loads) -------
    #pragma unroll
    for (int jt2 = tid; jt2 < NN / 2; jt2 += 128) {
        int4 e4 = nrow4[jt2];
        #pragma unroll
        for (int h = 0; h < 2; h++) {
            int jt = jt2 * 2 + h;
            float dx = ppos[jt * 3 + 0] - pix;
            float dy = ppos[jt * 3 + 1] - piy;
            float dz = ppos[jt * 3 + 2] - piz;
            float dist = sqrtf(dx * dx + dy * dy + dz * dz);
            float rinv = __fdividef(1.0f, dist + 1e-5f);
            dpo[jt * 3 + 0] = dx * rinv;
            dpo[jt * 3 + 1] = dy * rinv;
            dpo[jt * 3 + 2] = dz * rinv;

            int exi = h ? e4.z : e4.x;
            int eyi = h ? e4.w : e4.y;
            int aa_j = maskv(aa_m, b * NN + jt, isb);
            float2 t0 = tbl[aa_i ? 0 : exi];
            float2 t1 = tbl[aa_j ? 0 : eyi];
            float mul = t0.x + t1.x;
            float bia = t0.y + t1.y;

            int padj = maskv(pad_m, b * NN + jt, isb);
            int md   = mp_i | maskv(pos_m, b * NN + jt, isb);
            pk[jt] = make_float4(fmaf(mul, dist, bia),
                                 padj ? 0.0f : 1.0f,
                                 md   ? 1.0f : 0.0f, 0.0f);
        }
    }
    __syncthreads();

    // ---- wait for timestep encoder (block 0) -------------------------------
    if (tid == 0) {
        while (*(volatile int*)&g_flag == 0) __nanosleep(64);
    }
    __syncthreads();

    // ---- per-thread k-quad parameters (t vectors via L2 to skip stale L1) --
    const int k0 = lane * 4;
    float4 mn = *(const float4*)(means + k0);
    float4 sd = *(const float4*)(stds + k0);
    float is_x = 1.0f / (fabsf(sd.x) + 0.01f);
    float is_y = 1.0f / (fabsf(sd.y) + 0.01f);
    float is_z = 1.0f / (fabsf(sd.z) + 0.01f);
    float is_w = 1.0f / (fabsf(sd.w) + 0.01f);
    const float inv_a = 0.39894290f;           // 1/sqrt(2*3.14159)
    float cf_x = is_x * inv_a, cf_y = is_y * inv_a, cf_z = is_z * inv_a, cf_w = is_w * inv_a;
    float mi_x = mn.x * is_x, mi_y = mn.y * is_y, mi_z = mn.z * is_z, mi_w = mn.w * is_w;

    float4 t2v  = __ldcg((const float4*)(&g_t2[b][k0]));
    float4 t02v = __ldcg((const float4*)(&g_t02[k0]));
    float dt_x = t2v.x - t02v.x, dt_y = t2v.y - t02v.y;
    float dt_z = t2v.z - t02v.z, dt_w = t2v.w - t02v.w;

    float* efb = out + OFF_EF + ((size_t)(b * NN + i)) * (size_t)(NN * KK);
    float4 acc = make_float4(0.f, 0.f, 0.f, 0.f);
    const float4 zero4 = make_float4(0.f, 0.f, 0.f, 0.f);

    // ---- Phase 2: warp owns j%4, lane owns k-quad. Branch is warp-uniform. --
    #pragma unroll 8
    for (int jb = 0; jb < NN / 4; jb++) {
        int j = jb * 4 + warp;
        float4 p = pk[j];
        float4* dst = (float4*)(efb + (size_t)j * KK + k0);

        if (p.y == 0.0f) {
            __stcs(dst, zero4);               // padded j: whole K row zero
        } else {
            float x = p.x, mdf = p.z;

            float zx = fmaf(x, is_x, -mi_x);
            float zy = fmaf(x, is_y, -mi_y);
            float zz = fmaf(x, is_z, -mi_z);
            float zw = fmaf(x, is_w, -mi_w);
            float gx = __expf(zx * zx * -0.5f);
            float gy = __expf(zy * zy * -0.5f);
            float gz = __expf(zz * zz * -0.5f);
            float gw = __expf(zw * zw * -0.5f);

            float4 r;
            r.x = fmaf(gx, cf_x, fmaf(mdf, dt_x, t02v.x));
            r.y = fmaf(gy, cf_y, fmaf(mdf, dt_y, t02v.y));
            r.z = fmaf(gz, cf_z, fmaf(mdf, dt_z, t02v.z));
            r.w = fmaf(gw, cf_w, fmaf(mdf, dt_w, t02v.w));

            acc.x += r.x; acc.y += r.y; acc.z += r.z; acc.w += r.w;
            __stcs(dst, r);
        }
    }

    // ---- row-sum reduction across the 4 warps ------------------------------
    partial[warp][lane] = acc;
    __syncthreads();
    if (warp == 0) {
        float4 a0 = partial[0][lane], a1 = partial[1][lane];
        float4 a2 = partial[2][lane], a3 = partial[3][lane];
        float4 s = make_float4(a0.x + a1.x + a2.x + a3.x,
                               a0.y + a1.y + a2.y + a3.y,
                               a0.z + a1.z + a2.z + a3.z,
                               a0.w + a1.w + a2.w + a3.w);
        *(float4*)(&g_sum[((size_t)(b * NN + i)) * KK + k0]) = s;
    }

    // ---- self-reset of flag/done for the next graph replay -----------------
    if (tid == 0) {
        int old = atomicAdd(&g_done, 1);
        if (old == BB * NN - 1) {            // last edge block out
            g_done = 0;
            __threadfence();
            *(volatile int*)&g_flag = 0;
        }
    }
}

// ---------------------------------------------------------------------------
// Kernel 3: merge = sum_edge_features @ proj_w + proj_b (zero padded rows).
// Latency-optimized with EXPLICIT register prefetch arrays: each k-chunk of 8
// batches 8 LDG.128 (w) + 8 LDS.64 (s) before any FMA -> MLP ~12 guaranteed
// by register allocation, not by pragma.
// Tile 8 rows x 256 cols, grid (128, 3); thread owns e-quad x 2 rows.
// ---------------------------------------------------------------------------
__global__ void __launch_bounds__(256) proj_kernel(
    const float* __restrict__ pw, const float* __restrict__ pb,
    const void* __restrict__ pad_m, float* __restrict__ out)
{
    __shared__ __align__(16) float s_t[KK * 8];    // [k][row], 4KB
    const int bx  = blockIdx.x;                    // row tile (8 rows)
    const int tid = threadIdx.x;
    const int eq  = tid & 63;                      // e-quad within 256-col tile
    const int rg  = tid >> 6;                      // row-group 0..3 (2 rows each)
    const int e0  = blockIdx.y * 256 + eq * 4;

    // load 8 rows of g_sum, transposed to [k][row]
    for (int idx = tid; idx < 8 * KK; idx += 256) {
        int row = idx >> 7;          // 0..7
        int k   = idx & 127;
        s_t[k * 8 + row] = g_sum[(size_t)bx * 8 * KK + idx];
    }
    __syncthreads();

    const float* pwp = pw + e0;
    float4 acc0 = make_float4(0.f, 0.f, 0.f, 0.f);
    float4 acc1 = make_float4(0.f, 0.f, 0.f, 0.f);

    for (int kb = 0; kb < KK; kb += 8) {
        float4 w[8];
        float2 sv[8];
        // batch-issue all 16 loads (explicit arrays force live registers)
        #pragma unroll
        for (int p = 0; p < 8; p++)
            w[p] = *(const float4*)(pwp + (size_t)(kb + p) * EE);
        #pragma unroll
        for (int p = 0; p < 8; p++)
            sv[p] = *(const float2*)(s_t + (kb + p) * 8 + rg * 2);
        // then consume
        #pragma unroll
        for (int p = 0; p < 8; p++) {
            acc0.x = fmaf(sv[p].x, w[p].x, acc0.x);
            acc0.y = fmaf(sv[p].x, w[p].y, acc0.y);
            acc0.z = fmaf(sv[p].x, w[p].z, acc0.z);
            acc0.w = fmaf(sv[p].x, w[p].w, acc0.w);
            acc1.x = fmaf(sv[p].y, w[p].x, acc1.x);
            acc1.y = fmaf(sv[p].y, w[p].y, acc1.y);
            acc1.z = fmaf(sv[p].y, w[p].z, acc1.z);
            acc1.w = fmaf(sv[p].y, w[p].w, acc1.w);
        }
    }

    float4 bias = *(const float4*)(pb + e0);
    int isb = g_mask_is_byte;

    {
        int row = bx * 8 + rg * 2;
        int pm = maskv(pad_m, row, isb);
        float4 r = pm ? make_float4(0.f, 0.f, 0.f, 0.f)
                      : make_float4(acc0.x + bias.x, acc0.y + bias.y,
                                    acc0.z + bias.z, acc0.w + bias.w);
        *(float4*)(out + OFF_MERGE + (size_t)row * EE + e0) = r;
    }
    {
        int row = bx * 8 + rg * 2 + 1;
        int pm = maskv(pad_m, row, isb);
        float4 r = pm ? make_float4(0.f, 0.f, 0.f, 0.f)
                      : make_float4(acc1.x + bias.x, acc1.y + bias.y,
                                    acc1.z + bias.z, acc1.w + bias.w);
        *(float4*)(out + OFF_MERGE + (size_t)row * EE + e0) = r;
    }
}

// ---------------------------------------------------------------------------
extern "C" void kernel_launch(void* const* d_in, const int* in_sizes, int n_in,
                              void* d_out, int out_size)
{
    const float* pos    = (const float*)d_in[0];
    const int*   nte    = (const int*)  d_in[1];
    const void*  pad_m  = d_in[2];
    const void*  aa_m   = d_in[3];
    const void*  pos_m  = d_in[4];
    const int*   time_p = (const int*)  d_in[5];
    const float* means  = (const float*)d_in[6];
    const float* stds   = (const float*)d_in[7];
    const float* mul_w  = (const float*)d_in[8];
    const float* bias_w = (const float*)d_in[9];
    const float* proj_w = (const float*)d_in[10];
    const float* proj_b = (const float*)d_in[11];
    const float* t_w1   = (const float*)d_in[12];
    const float* t_b1   = (const float*)d_in[13];
    const float* t_w2   = (const float*)d_in[14];
    const float* t_b2   = (const float*)d_in[15];
    float* out = (float*)d_out;

    fused_kernel<<<BB * NN + 1, 128>>>(pos, nte, pad_m, aa_m, pos_m, time_p,
                                       means, stds, mul_w, bias_w,
                                       t_w1, t_b1, t_w2, t_b2, out);
    proj_kernel<<<dim3((BB * NN) / 8, EE / 256), 256>>>(proj_w, proj_b, pad_m, out);
}